// round 3
// baseline (speedup 1.0000x reference)
#include <cuda_runtime.h>
#include <cuda_bf16.h>

#define B_  64
#define C_  1024
#define HW_ 1024
#define CSPLIT 8          // channel chunks for score partials
#define GB 16             // batches per pipeline group (64 MB of x)
#define POOL_CPB 32       // pool CTAs per batch (32 channels each)
#define SC_CPB 32         // scores CTAs per batch (8 channel-chunks x 4 hw-quarters)

// Scratch: partial scores (no device allocations allowed).
__device__ float g_partial[B_ * CSPLIT * HW_];   // 2 MB

// ---------------------------------------------------------------------------
// One fused kernel. Blocks [0, n_pool_b*POOL_CPB) do pooling (with an inlined
// per-CTA softmax over the score partials) for batches [pool_b0, +n_pool_b).
// Remaining blocks compute score partials for batches [sc_b0, +n_sc_b).
// Branch is uniform per block (on blockIdx), so __syncthreads stays legal.
// ---------------------------------------------------------------------------
__global__ __launch_bounds__(256) void fused_kernel(
    const float* __restrict__ x, const float* __restrict__ w,
    float* __restrict__ out,
    int pool_b0, int n_pool_b, int sc_b0, int n_sc_b)
{
    __shared__ float s_attn[HW_];   // 4 KB attention weights for this batch
    __shared__ float s_red[8];

    const int poolCnt = n_pool_b * POOL_CPB;

    if ((int)blockIdx.x >= poolCnt) {
        // ------------------ scores: partial dot over 128 channels ----------
        const int idx = blockIdx.x - poolCnt;
        const int b   = sc_b0 + (idx >> 5);
        const int r   = idx & 31;
        const int cs  = r >> 2;               // 0..7  channel chunk
        const int q   = r & 3;                // 0..3  hw quarter
        const int hw  = q * 256 + threadIdx.x;
        const int c0  = cs * 128;

        const float* xb = x + ((size_t)(b * C_ + c0)) * HW_ + hw;
        float acc = 0.f;
        #pragma unroll 16
        for (int c = 0; c < 128; ++c)
            acc = fmaf(xb[(size_t)c * HW_], __ldg(&w[c0 + c]), acc);
        g_partial[((b * CSPLIT + cs) << 10) + hw] = acc;
        return;
    }

    // ------------------ pool: local softmax + weighted spatial sum --------
    const int b  = pool_b0 + ((int)blockIdx.x >> 5);
    const int cc = blockIdx.x & 31;           // 32-channel chunk
    const int t    = threadIdx.x;
    const int lane = t & 31;
    const int warp = t >> 5;

    // Phase A: reduce CSPLIT partials, softmax over HW (bias cancels in softmax)
    const float* pb = g_partial + ((size_t)b * CSPLIT) * HW_;
    float4 s = reinterpret_cast<const float4*>(pb)[t];
    #pragma unroll
    for (int cs = 1; cs < CSPLIT; ++cs) {
        const float4 p = reinterpret_cast<const float4*>(pb + (size_t)cs * HW_)[t];
        s.x += p.x; s.y += p.y; s.z += p.z; s.w += p.w;
    }

    float m = fmaxf(fmaxf(s.x, s.y), fmaxf(s.z, s.w));
    #pragma unroll
    for (int o = 16; o; o >>= 1) m = fmaxf(m, __shfl_xor_sync(~0u, m, o));
    if (lane == 0) s_red[warp] = m;
    __syncthreads();
    if (warp == 0) {
        float v = s_red[lane & 7];
        #pragma unroll
        for (int o = 4; o; o >>= 1) v = fmaxf(v, __shfl_xor_sync(~0u, v, o));
        if (lane == 0) s_red[0] = v;
    }
    __syncthreads();
    const float M = s_red[0];
    __syncthreads();

    float4 e;
    e.x = __expf(s.x - M); e.y = __expf(s.y - M);
    e.z = __expf(s.z - M); e.w = __expf(s.w - M);

    float sum = e.x + e.y + e.z + e.w;
    #pragma unroll
    for (int o = 16; o; o >>= 1) sum += __shfl_xor_sync(~0u, sum, o);
    if (lane == 0) s_red[warp] = sum;
    __syncthreads();
    if (warp == 0) {
        float v = s_red[lane & 7];
        #pragma unroll
        for (int o = 4; o; o >>= 1) v += __shfl_xor_sync(~0u, v, o);
        if (lane == 0) s_red[0] = v;
    }
    __syncthreads();
    const float Zinv = 1.0f / s_red[0];

    float4 a;
    a.x = e.x * Zinv; a.y = e.y * Zinv; a.z = e.z * Zinv; a.w = e.w * Zinv;
    reinterpret_cast<float4*>(s_attn)[t] = a;
    __syncthreads();

    // Phase B: 8 warps x 4 rows each -> 32 channels.
    const float4* at4 = reinterpret_cast<const float4*>(s_attn);
    #pragma unroll
    for (int rr = 0; rr < 4; ++rr) {
        const int row = cc * 32 + warp * 4 + rr;       // channel within batch
        const float4* xr = reinterpret_cast<const float4*>(
            x + ((size_t)(b * C_ + row)) * HW_);
        float acc = 0.f;
        #pragma unroll
        for (int i = 0; i < 8; ++i) {
            const float4 v  = xr[lane + i * 32];
            const float4 aw = at4[lane + i * 32];
            acc += v.x * aw.x + v.y * aw.y + v.z * aw.z + v.w * aw.w;
        }
        #pragma unroll
        for (int o = 16; o; o >>= 1) acc += __shfl_xor_sync(~0u, acc, o);
        if (lane == 0) out[b * C_ + row] = acc;
    }
}

// ---------------------------------------------------------------------------
extern "C" void kernel_launch(void* const* d_in, const int* in_sizes, int n_in,
                              void* d_out, int out_size)
{
    const float* x = (const float*)d_in[0];
    const float* w = (const float*)d_in[1];
    float* out     = (float*)d_out;

    // Pipeline over 4 groups of GB=16 batches:
    //   S(g0) ; [P(g0)+S(g1)] ; [P(g1)+S(g2)] ; [P(g2)+S(g3)] ; P(g3)
    fused_kernel<<<GB * SC_CPB, 256>>>(x, w, out, 0, 0, 0, GB);
    for (int g = 0; g < 3; ++g)
        fused_kernel<<<GB * POOL_CPB + GB * SC_CPB, 256>>>(
            x, w, out, g * GB, GB, (g + 1) * GB, GB);
    fused_kernel<<<GB * POOL_CPB, 256>>>(x, w, out, 3 * GB, GB, 0, 0);
}